// round 6
// baseline (speedup 1.0000x reference)
#include <cuda_runtime.h>
#include <cstdint>

#define RADIUS 4
#define DD 9
#define NB 16
#define NC 256
#define NH 96
#define NW 96
#define HW (NH * NW)
#define TYR 2                 // output rows per CTA
#define PX 8                  // pixels per thread along x
#define NG (NW / PX)          // 12
#define CC 8                  // channels per chunk
#define NCHUNK (NC / CC)      // 32
#define NCOMPUTE (NG * DD * TYR)  // 216
#define BLOCK 256
#define TH (TYR + 2 * RADIUS)     // 10 halo rows

// ---- padded, swizzle-friendly smem layout (byte units) ----
#define TROW_B 416                // 104 floats per t row
#define TCH_B  5120               // t channel stride (mult of 1024)
#define TREG_B (CC * TCH_B)       // 40960
#define SROW_B 384                // 96 floats per s row
#define SCH_B  1024               // s channel stride (mult of 1024)
#define SREG_B (CC * SCH_B)       // 8192
#define BUF_B  (TREG_B + SREG_B)  // 49152
#define SMEM_B (2 * BUF_B)        // 98304

#define SWZ(x) ((x) ^ ((((x) >> 7) & 7) << 4))

#define T_SLOTS (CC * TH * 24)    // 1920 float4s per chunk
#define S_SLOTS (CC * TYR * 24)   // 384

union F2U { float2 f; unsigned long long u; };

__device__ __forceinline__ float2 ffma2(float2 a, float2 b, float2 c) {
    F2U ua, ub, uc, ud;
    ua.f = a; ub.f = b; uc.f = c;
    asm("fma.rn.f32x2 %0, %1, %2, %3;"
        : "=l"(ud.u) : "l"(ua.u), "l"(ub.u), "l"(uc.u));
    return ud.f;
}

__device__ __forceinline__ void cp16(uint32_t dst_smem, const void* src) {
    asm volatile("cp.async.cg.shared.global [%0], [%1], 16;\n"
                 :: "r"(dst_smem), "l"(src));
}
__device__ __forceinline__ void cp_commit() {
    asm volatile("cp.async.commit_group;\n" ::: "memory");
}
__device__ __forceinline__ void cp_wait1() {
    asm volatile("cp.async.wait_group 1;\n" ::: "memory");
}
__device__ __forceinline__ void cp_wait0() {
    asm volatile("cp.async.wait_group 0;\n" ::: "memory");
}

__global__ __launch_bounds__(BLOCK, 2)
void corr_kernel(const float* __restrict__ fs, const float* __restrict__ ft,
                 float* __restrict__ out)
{
    extern __shared__ char smem[];

    const int b   = blockIdx.y;
    const int y0  = blockIdx.x * TYR;
    const int tid = threadIdx.x;
    const int g   = tid % NG;
    const int dy  = (tid / NG) % DD;
    const int r   = (tid / (NG * DD)) & 1;   // safe junk for tid>=216
    const bool active = (tid < NCOMPUTE);

    const uint32_t smem_s = (uint32_t)__cvta_generic_to_shared(smem);

    // ---- hoisted staging slot tables (computed once) ----
    uint32_t tdst[8], tsrc[8];
    int tn = 0;
#pragma unroll
    for (int i = 0; i < 8; ++i) {
        int slot = tid + i * BLOCK;
        if (slot < T_SLOTS) {
            int c   = slot / (TH * 24);
            int rem = slot - c * (TH * 24);
            int ro  = rem / 24;
            int q   = rem - ro * 24;
            int gr  = y0 + ro - RADIUS;
            if ((unsigned)gr < NH) {
                uint32_t off = (uint32_t)(ro * TROW_B + 16 + 16 * q);
                tdst[tn] = (uint32_t)(c * TCH_B) + SWZ(off);
                tsrc[tn] = (uint32_t)((c * HW + gr * NW + 4 * q) * 4);
                ++tn;
            }
        }
    }
    uint32_t sdst[2], ssrc[2];
    int sn = 0;
#pragma unroll
    for (int i = 0; i < 2; ++i) {
        int slot = tid + i * BLOCK;
        if (slot < S_SLOTS) {
            int c   = slot / (TYR * 24);
            int rem = slot - c * (TYR * 24);
            int ro  = rem / 24;
            int q   = rem - ro * 24;
            uint32_t off = (uint32_t)(ro * SROW_B + 16 * q);
            sdst[sn] = (uint32_t)(TREG_B + c * SCH_B) + SWZ(off);
            ssrc[sn] = (uint32_t)((c * HW + (y0 + ro) * NW + 4 * q) * 4);
            ++sn;
        }
    }

    // ---- hoisted swizzled read offsets ----
    uint32_t t_off[4], s_off[2];
#pragma unroll
    for (int q = 0; q < 4; ++q)
        t_off[q] = SWZ((uint32_t)((r + dy) * TROW_B + 32 * g + 16 * q));
#pragma unroll
    for (int q = 0; q < 2; ++q)
        s_off[q] = (uint32_t)TREG_B + SWZ((uint32_t)(r * SROW_B + 32 * g + 16 * q));

    // zero smem once: halo padding stays zero forever
    for (int i = tid * 4; i < SMEM_B / 4; i += BLOCK * 4)
        *(float4*)(smem + i * 4) = make_float4(0.f, 0.f, 0.f, 0.f);
    __syncthreads();

    float2 acc2[4][DD];
#pragma unroll
    for (int pp = 0; pp < 4; ++pp)
#pragma unroll
        for (int dx = 0; dx < DD; ++dx) acc2[pp][dx] = make_float2(0.f, 0.f);

    const char* fs_b = (const char*)(fs + (size_t)b * NC * HW);
    const char* ft_b = (const char*)(ft + (size_t)b * NC * HW);

    // ---- prologue: stage chunk 0
    {
#pragma unroll
        for (int i = 0; i < 8; ++i)
            if (i < tn) cp16(smem_s + tdst[i], ft_b + tsrc[i]);
#pragma unroll
        for (int i = 0; i < 2; ++i)
            if (i < sn) cp16(smem_s + sdst[i], fs_b + ssrc[i]);
        cp_commit();
    }

    for (int k = 0; k < NCHUNK; ++k) {
        const uint32_t cur = (uint32_t)(k & 1);
        if (k + 1 < NCHUNK) {
            const uint32_t nb = (cur ^ 1) * BUF_B;
            const uint32_t koff = (uint32_t)(k + 1) * (CC * HW * 4);
#pragma unroll
            for (int i = 0; i < 8; ++i)
                if (i < tn) cp16(smem_s + nb + tdst[i], ft_b + koff + tsrc[i]);
#pragma unroll
            for (int i = 0; i < 2; ++i)
                if (i < sn) cp16(smem_s + nb + sdst[i], fs_b + koff + ssrc[i]);
            cp_commit();
            cp_wait1();
        } else {
            cp_wait0();
        }
        __syncthreads();

        if (active) {
            const char* bb = smem + cur * BUF_B;
#pragma unroll
            for (int c = 0; c < CC; ++c) {
                const char* tb = bb + c * TCH_B;
                const char* sb = bb + c * SCH_B;

                float4 T0 = *(const float4*)(tb + t_off[0]);
                float4 T1 = *(const float4*)(tb + t_off[1]);
                float4 T2 = *(const float4*)(tb + t_off[2]);
                float4 T3 = *(const float4*)(tb + t_off[3]);
                float4 S0 = *(const float4*)(sb + s_off[0]);
                float4 S1 = *(const float4*)(sb + s_off[1]);

                float2 te[8] = { {T0.x,T0.y},{T0.z,T0.w},{T1.x,T1.y},{T1.z,T1.w},
                                 {T2.x,T2.y},{T2.z,T2.w},{T3.x,T3.y},{T3.z,T3.w} };
                float2 se[4] = { {S0.x,S0.y},{S0.z,S0.w},{S1.x,S1.y},{S1.z,S1.w} };

#pragma unroll
                for (int pp = 0; pp < 4; ++pp) {
#pragma unroll
                    for (int m = 0; m <= 4; ++m)
                        acc2[pp][2 * m] = ffma2(se[pp], te[pp + m], acc2[pp][2 * m]);
#pragma unroll
                    for (int m = 0; m < 4; ++m) {
                        acc2[pp][2 * m + 1].x =
                            fmaf(se[pp].x, te[pp + m].y,     acc2[pp][2 * m + 1].x);
                        acc2[pp][2 * m + 1].y =
                            fmaf(se[pp].y, te[pp + m + 1].x, acc2[pp][2 * m + 1].y);
                    }
                }
            }
        }
        __syncthreads();
    }

    if (active) {
        const float scale = 1.0f / (float)NC;
        const int y  = y0 + r;
        const int x0 = g * PX;
        float* ob = out + (((size_t)b * (DD * DD) + dy * DD) * NH + y) * NW + x0;
#pragma unroll
        for (int dx = 0; dx < DD; ++dx) {
            float4 o0, o1;
            o0.x = acc2[0][dx].x * scale;
            o0.y = acc2[0][dx].y * scale;
            o0.z = acc2[1][dx].x * scale;
            o0.w = acc2[1][dx].y * scale;
            o1.x = acc2[2][dx].x * scale;
            o1.y = acc2[2][dx].y * scale;
            o1.z = acc2[3][dx].x * scale;
            o1.w = acc2[3][dx].y * scale;
            float* op = ob + (size_t)dx * HW;
            *(float4*)(op)     = o0;
            *(float4*)(op + 4) = o1;
        }
    }
}

extern "C" void kernel_launch(void* const* d_in, const int* in_sizes, int n_in,
                              void* d_out, int out_size)
{
    const float* fs = (const float*)d_in[0];   // feat_s
    const float* ft = (const float*)d_in[1];   // feat_t
    float* out = (float*)d_out;

    cudaFuncSetAttribute(corr_kernel, cudaFuncAttributeMaxDynamicSharedMemorySize,
                         SMEM_B);

    dim3 grid(NH / TYR, NB);   // (48, 16)
    corr_kernel<<<grid, BLOCK, SMEM_B>>>(fs, ft, out);
}

// round 8
// speedup vs baseline: 1.5245x; 1.5245x over previous
#include <cuda_runtime.h>
#include <cstdint>

#define RADIUS 4
#define DD 9
#define NB 16
#define NC 256
#define NH 96
#define NW 96
#define HW (NH * NW)
#define TYR 2                 // output rows per CTA
#define PX 8                  // pixels per thread along x
#define NG (NW / PX)          // 12
#define CC 8                  // channels per chunk
#define NCHUNK (NC / CC)      // 32
#define NCOMPUTE (NG * DD * TYR)  // 216
#define BLOCK 224
#define TH (TYR + 2 * RADIUS)     // 10 halo rows

// t rows: 27 chunks of 16B (432 B; 27 mod 8 = 3 -> dy-groups rotate columns by 3)
// s rows: 24 chunks (384 B)
#define TROW_B 432
#define TCH_B  (TH * TROW_B)       // 4320
#define TREG_B (CC * TCH_B)        // 34560
#define SROW_B 384
#define SCH_B  (TYR * SROW_B)      // 768
#define SREG_B (CC * SCH_B)        // 6144
#define BUF_B  (TREG_B + SREG_B)   // 40704
#define SMEM_B (2 * BUF_B)         // 81408

// chunk permutation: XOR-swizzle inside full 8-blocks (j<24), identity above.
// Closed over 0..26 for t rows and 0..23 for s rows.
#define PSW(j) (((j) < 24) ? ((j) ^ (((j) >> 3) & 3)) : (j))

#define T_SLOTS (CC * TH * 24)     // 1920 valid float4s per chunk
#define S_SLOTS (CC * TYR * 24)    // 384

union F2U { float2 f; unsigned long long u; };

__device__ __forceinline__ float2 ffma2(float2 a, float2 b, float2 c) {
    F2U ua, ub, uc, ud;
    ua.f = a; ub.f = b; uc.f = c;
    asm("fma.rn.f32x2 %0, %1, %2, %3;"
        : "=l"(ud.u) : "l"(ua.u), "l"(ub.u), "l"(uc.u));
    return ud.f;
}

__device__ __forceinline__ void cp16(uint32_t dst_smem, const void* src) {
    asm volatile("cp.async.cg.shared.global [%0], [%1], 16;\n"
                 :: "r"(dst_smem), "l"(src));
}
__device__ __forceinline__ void cp_commit() {
    asm volatile("cp.async.commit_group;\n" ::: "memory");
}
__device__ __forceinline__ void cp_wait1() {
    asm volatile("cp.async.wait_group 1;\n" ::: "memory");
}
__device__ __forceinline__ void cp_wait0() {
    asm volatile("cp.async.wait_group 0;\n" ::: "memory");
}

// Stage one 8-channel chunk (inline math, register-light).
__device__ __forceinline__ void stage_chunk(
    uint32_t buf_s, const char* __restrict__ ft_k, const char* __restrict__ fs_k,
    int y0, int tid)
{
    for (int slot = tid; slot < T_SLOTS; slot += BLOCK) {
        int c   = slot / (TH * 24);
        int rem = slot - c * (TH * 24);
        int ro  = rem / 24;
        int q   = rem - ro * 24;
        int gr  = y0 + ro - RADIUS;
        if ((unsigned)gr < NH) {
            int j = q + 1;                 // logical chunk: smem cols 4j..4j+3
            uint32_t dst = (uint32_t)(c * TCH_B + ro * TROW_B + (PSW(j) << 4));
            cp16(buf_s + dst, ft_k + (size_t)(c * HW + gr * NW + 4 * q) * 4);
        }
    }
    for (int slot = tid; slot < S_SLOTS; slot += BLOCK) {
        int c   = slot / (TYR * 24);
        int rem = slot - c * (TYR * 24);
        int ro  = rem / 24;
        int q   = rem - ro * 24;
        uint32_t dst = (uint32_t)(TREG_B + c * SCH_B + ro * SROW_B + (PSW(q) << 4));
        cp16(buf_s + dst, fs_k + (size_t)(c * HW + (y0 + ro) * NW + 4 * q) * 4);
    }
}

__global__ __launch_bounds__(BLOCK, 2)
void corr_kernel(const float* __restrict__ fs, const float* __restrict__ ft,
                 float* __restrict__ out)
{
    extern __shared__ char smem[];

    const int b   = blockIdx.y;
    const int y0  = blockIdx.x * TYR;
    const int tid = threadIdx.x;
    const int g   = tid % NG;
    const int dy  = (tid / NG) % DD;
    const int r   = (tid / (NG * DD)) & 1;
    const bool active = (tid < NCOMPUTE);

    const uint32_t smem_s = (uint32_t)__cvta_generic_to_shared(smem);

    // hoisted swizzled read offsets (6 regs)
    // t: chunks 2g..2g+3 of row r+dy;  s: chunks 2g,2g+1 of row r
    uint32_t t_off[4], s_off[2];
#pragma unroll
    for (int q = 0; q < 4; ++q)
        t_off[q] = (uint32_t)((r + dy) * TROW_B + (PSW(2 * g + q) << 4));
#pragma unroll
    for (int q = 0; q < 2; ++q)
        s_off[q] = (uint32_t)(TREG_B + r * SROW_B + (PSW(2 * g + q) << 4));

    // zero smem once: halo padding stays zero for all chunks
    for (int i = tid; i < SMEM_B / 16; i += BLOCK)
        *(float4*)(smem + i * 16) = make_float4(0.f, 0.f, 0.f, 0.f);
    __syncthreads();

    float2 acc2[4][DD];
#pragma unroll
    for (int pp = 0; pp < 4; ++pp)
#pragma unroll
        for (int dx = 0; dx < DD; ++dx) acc2[pp][dx] = make_float2(0.f, 0.f);

    const char* fs_b = (const char*)(fs + (size_t)b * NC * HW);
    const char* ft_b = (const char*)(ft + (size_t)b * NC * HW);

    stage_chunk(smem_s, ft_b, fs_b, y0, tid);
    cp_commit();

    for (int k = 0; k < NCHUNK; ++k) {
        const uint32_t cur = (uint32_t)(k & 1);
        if (k + 1 < NCHUNK) {
            const size_t koff = (size_t)(k + 1) * (CC * HW * 4);
            stage_chunk(smem_s + (cur ^ 1) * BUF_B, ft_b + koff, fs_b + koff,
                        y0, tid);
            cp_commit();
            cp_wait1();
        } else {
            cp_wait0();
        }
        __syncthreads();

        if (active) {
            const char* bb = smem + cur * BUF_B;
#pragma unroll
            for (int c = 0; c < CC; ++c) {
                const char* tb = bb + c * TCH_B;
                const char* sb = bb + c * SCH_B;

                float4 T0 = *(const float4*)(tb + t_off[0]);
                float4 T1 = *(const float4*)(tb + t_off[1]);
                float4 T2 = *(const float4*)(tb + t_off[2]);
                float4 T3 = *(const float4*)(tb + t_off[3]);
                float4 S0 = *(const float4*)(sb + s_off[0]);
                float4 S1 = *(const float4*)(sb + s_off[1]);

                float2 te[8] = { {T0.x,T0.y},{T0.z,T0.w},{T1.x,T1.y},{T1.z,T1.w},
                                 {T2.x,T2.y},{T2.z,T2.w},{T3.x,T3.y},{T3.z,T3.w} };
                float2 se[4] = { {S0.x,S0.y},{S0.z,S0.w},{S1.x,S1.y},{S1.z,S1.w} };

#pragma unroll
                for (int pp = 0; pp < 4; ++pp) {
#pragma unroll
                    for (int m = 0; m <= 4; ++m)
                        acc2[pp][2 * m] = ffma2(se[pp], te[pp + m], acc2[pp][2 * m]);
#pragma unroll
                    for (int m = 0; m < 4; ++m) {
                        acc2[pp][2 * m + 1].x =
                            fmaf(se[pp].x, te[pp + m].y,     acc2[pp][2 * m + 1].x);
                        acc2[pp][2 * m + 1].y =
                            fmaf(se[pp].y, te[pp + m + 1].x, acc2[pp][2 * m + 1].y);
                    }
                }
            }
        }
        __syncthreads();
    }

    if (active) {
        const float scale = 1.0f / (float)NC;
        const int y  = y0 + r;
        const int x0 = g * PX;
        float* ob = out + (((size_t)b * (DD * DD) + dy * DD) * NH + y) * NW + x0;
#pragma unroll
        for (int dx = 0; dx < DD; ++dx) {
            float4 o0, o1;
            o0.x = acc2[0][dx].x * scale;
            o0.y = acc2[0][dx].y * scale;
            o0.z = acc2[1][dx].x * scale;
            o0.w = acc2[1][dx].y * scale;
            o1.x = acc2[2][dx].x * scale;
            o1.y = acc2[2][dx].y * scale;
            o1.z = acc2[3][dx].x * scale;
            o1.w = acc2[3][dx].y * scale;
            float* op = ob + (size_t)dx * HW;
            *(float4*)(op)     = o0;
            *(float4*)(op + 4) = o1;
        }
    }
}

extern "C" void kernel_launch(void* const* d_in, const int* in_sizes, int n_in,
                              void* d_out, int out_size)
{
    const float* fs = (const float*)d_in[0];   // feat_s
    const float* ft = (const float*)d_in[1];   // feat_t
    float* out = (float*)d_out;

    cudaFuncSetAttribute(corr_kernel, cudaFuncAttributeMaxDynamicSharedMemorySize,
                         SMEM_B);

    dim3 grid(NH / TYR, NB);   // (48, 16)
    corr_kernel<<<grid, BLOCK, SMEM_B>>>(fs, ft, out);
}

// round 9
// speedup vs baseline: 1.6366x; 1.0735x over previous
#include <cuda_runtime.h>
#include <cstdint>

#define RADIUS 4
#define DD 9
#define NB 16
#define NC 256
#define NH 96
#define NW 96
#define HW (NH * NW)
#define TYR 2                 // output rows per CTA
#define PX 8                  // pixels per thread along x
#define NG (NW / PX)          // 12
#define CC 8                  // channels per chunk
#define NCHUNK (NC / CC)      // 32
#define NCOMPUTE (NG * DD * TYR)  // 216
#define BLOCK 256
#define TH (TYR + 2 * RADIUS)     // 10 halo rows
#define CHUNK_B (CC * HW * 4)     // global bytes per chunk per tensor

// t rows: 27 chunks of 16B (432 B; 27 mod 8 = 3 -> dy-groups rotate columns)
// s rows: 24 chunks (384 B)
#define TROW_B 432
#define TCH_B  (TH * TROW_B)       // 4320
#define TREG_B (CC * TCH_B)        // 34560
#define SROW_B 384
#define SCH_B  (TYR * SROW_B)      // 768
#define SREG_B (CC * SCH_B)        // 6144
#define BUF_B  (TREG_B + SREG_B)   // 40704
#define SMEM_B (2 * BUF_B)         // 81408

// chunk permutation: XOR-swizzle inside full 8-blocks (j<24), identity above.
#define PSW(j) (((j) < 24) ? ((j) ^ (((j) >> 3) & 3)) : (j))

union F2U { float2 f; unsigned long long u; };

__device__ __forceinline__ float2 ffma2(float2 a, float2 b, float2 c) {
    F2U ua, ub, uc, ud;
    ua.f = a; ub.f = b; uc.f = c;
    asm("fma.rn.f32x2 %0, %1, %2, %3;"
        : "=l"(ud.u) : "l"(ua.u), "l"(ub.u), "l"(uc.u));
    return ud.f;
}

__device__ __forceinline__ void cp16(uint32_t dst_smem, const void* src) {
    asm volatile("cp.async.cg.shared.global [%0], [%1], 16;\n"
                 :: "r"(dst_smem), "l"(src));
}
__device__ __forceinline__ void cp_commit() {
    asm volatile("cp.async.commit_group;\n" ::: "memory");
}
__device__ __forceinline__ void cp_wait1() {
    asm volatile("cp.async.wait_group 1;\n" ::: "memory");
}
__device__ __forceinline__ void cp_wait0() {
    asm volatile("cp.async.wait_group 0;\n" ::: "memory");
}

// Ownership staging: each thread's slot offsets are precomputed once.
__device__ __forceinline__ void do_stage(
    uint32_t buf, const char* __restrict__ ftk, const char* __restrict__ fsk,
    bool t_valid, uint32_t t_dst0, uint32_t t_src0,
    bool s_stage, uint32_t s_dst0, uint32_t s_src0)
{
    if (t_valid) {
#pragma unroll
        for (int c = 0; c < CC; ++c)
            cp16(buf + t_dst0 + c * TCH_B, ftk + t_src0 + (size_t)c * (HW * 4));
    }
    if (s_stage) {
#pragma unroll
        for (int c = 0; c < CC; ++c)
            cp16(buf + s_dst0 + c * SCH_B, fsk + s_src0 + (size_t)c * (HW * 4));
    }
}

__global__ __launch_bounds__(BLOCK, 2)
void corr_kernel(const float* __restrict__ fs, const float* __restrict__ ft,
                 float* __restrict__ out)
{
    extern __shared__ char smem[];

    const int b   = blockIdx.y;
    const int y0  = blockIdx.x * TYR;
    const int tid = threadIdx.x;
    const int g   = tid % NG;
    const int dy  = (tid / NG) % DD;
    const int r   = (tid / (NG * DD)) & 1;
    const bool active = (tid < NCOMPUTE);

    const uint32_t smem_s = (uint32_t)__cvta_generic_to_shared(smem);

    // ---- staging ownership (computed once; ~4 regs) ----
    bool t_valid = false;
    uint32_t t_dst0 = 0, t_src0 = 0;
    if (tid < TH * 24) {                   // 240 t-slots
        int ro = tid / 24, q = tid - ro * 24;
        int gr = y0 + ro - RADIUS;
        t_valid = ((unsigned)gr < NH);
        t_dst0 = (uint32_t)(ro * TROW_B + (PSW(q + 1) << 4));
        t_src0 = (uint32_t)((gr * NW + 4 * q) * 4);
    }
    const bool s_stage = (tid >= 208);     // 48 s-slots on threads 208..255
    uint32_t s_dst0 = 0, s_src0 = 0;
    if (s_stage) {
        int i = tid - 208;
        int ro = i / 24, q = i - ro * 24;
        s_dst0 = (uint32_t)(TREG_B + ro * SROW_B + (PSW(q) << 4));
        s_src0 = (uint32_t)(((y0 + ro) * NW + 4 * q) * 4);
    }

    // ---- hoisted swizzled read offsets ----
    uint32_t t_off[4], s_off[2];
#pragma unroll
    for (int q = 0; q < 4; ++q)
        t_off[q] = (uint32_t)((r + dy) * TROW_B + (PSW(2 * g + q) << 4));
#pragma unroll
    for (int q = 0; q < 2; ++q)
        s_off[q] = (uint32_t)(TREG_B + r * SROW_B + (PSW(2 * g + q) << 4));

    // zero smem once: halo padding stays zero for all chunks
    for (int i = tid; i < SMEM_B / 16; i += BLOCK)
        *(float4*)(smem + i * 16) = make_float4(0.f, 0.f, 0.f, 0.f);
    __syncthreads();

    // accumulators: 72 scalars total
    float2 accE[4][5];                     // even dx=2m, pixel pairs (2pp,2pp+1)
    float2 accM[3][4];                     // odd dx=2m+1, pixel pairs (2j+1,2j+2)
    float  acc0[4], acc7[4];               // odd dx edges, pixels 0 and 7
#pragma unroll
    for (int pp = 0; pp < 4; ++pp)
#pragma unroll
        for (int m = 0; m < 5; ++m) accE[pp][m] = make_float2(0.f, 0.f);
#pragma unroll
    for (int j = 0; j < 3; ++j)
#pragma unroll
        for (int m = 0; m < 4; ++m) accM[j][m] = make_float2(0.f, 0.f);
#pragma unroll
    for (int m = 0; m < 4; ++m) { acc0[m] = 0.f; acc7[m] = 0.f; }

    const char* ft_k = (const char*)(ft + (size_t)b * NC * HW);
    const char* fs_k = (const char*)(fs + (size_t)b * NC * HW);

    do_stage(smem_s, ft_k, fs_k, t_valid, t_dst0, t_src0, s_stage, s_dst0, s_src0);
    cp_commit();
    ft_k += CHUNK_B; fs_k += CHUNK_B;

    for (int k = 0; k < NCHUNK; ++k) {
        const uint32_t cur = (uint32_t)(k & 1);
        if (k + 1 < NCHUNK) {
            do_stage(smem_s + (cur ^ 1) * BUF_B, ft_k, fs_k,
                     t_valid, t_dst0, t_src0, s_stage, s_dst0, s_src0);
            cp_commit();
            ft_k += CHUNK_B; fs_k += CHUNK_B;
            cp_wait1();
        } else {
            cp_wait0();
        }
        __syncthreads();

        if (active) {
            const char* bb = smem + cur * BUF_B;
#pragma unroll
            for (int c = 0; c < CC; ++c) {
                const char* tb = bb + c * TCH_B;
                const char* sb = bb + c * SCH_B;

                float4 T0 = *(const float4*)(tb + t_off[0]);
                float4 T1 = *(const float4*)(tb + t_off[1]);
                float4 T2 = *(const float4*)(tb + t_off[2]);
                float4 T3 = *(const float4*)(tb + t_off[3]);
                float4 S0 = *(const float4*)(sb + s_off[0]);
                float4 S1 = *(const float4*)(sb + s_off[1]);

                float2 te[8] = { {T0.x,T0.y},{T0.z,T0.w},{T1.x,T1.y},{T1.z,T1.w},
                                 {T2.x,T2.y},{T2.z,T2.w},{T3.x,T3.y},{T3.z,T3.w} };
                float2 se[4] = { {S0.x,S0.y},{S0.z,S0.w},{S1.x,S1.y},{S1.z,S1.w} };
                float2 sh[3] = { {S0.y,S0.z}, {S0.w,S1.x}, {S1.y,S1.z} };

                // even dx = 2m: pixel pair (2pp,2pp+1) x tt pair te[pp+m]
#pragma unroll
                for (int pp = 0; pp < 4; ++pp)
#pragma unroll
                    for (int m = 0; m < 5; ++m)
                        accE[pp][m] = ffma2(se[pp], te[pp + m], accE[pp][m]);
                // odd dx = 2m+1: pixel pair (2j+1,2j+2) x te[j+m+1]
#pragma unroll
                for (int j = 0; j < 3; ++j)
#pragma unroll
                    for (int m = 0; m < 4; ++m)
                        accM[j][m] = ffma2(sh[j], te[j + m + 1], accM[j][m]);
                // odd dx edges
#pragma unroll
                for (int m = 0; m < 4; ++m) {
                    acc0[m] = fmaf(se[0].x, te[m].y,     acc0[m]);
                    acc7[m] = fmaf(se[3].y, te[4 + m].x, acc7[m]);
                }
            }
        }
        __syncthreads();
    }

    if (active) {
        const float scale = 1.0f / (float)NC;
        const int y  = y0 + r;
        const int x0 = g * PX;
        float* ob = out + (((size_t)b * (DD * DD) + dy * DD) * NH + y) * NW + x0;
        // even dx = 2m
#pragma unroll
        for (int m = 0; m < 5; ++m) {
            float4 o0, o1;
            o0.x = accE[0][m].x * scale;  o0.y = accE[0][m].y * scale;
            o0.z = accE[1][m].x * scale;  o0.w = accE[1][m].y * scale;
            o1.x = accE[2][m].x * scale;  o1.y = accE[2][m].y * scale;
            o1.z = accE[3][m].x * scale;  o1.w = accE[3][m].y * scale;
            float* op = ob + (size_t)(2 * m) * HW;
            *(float4*)(op)     = o0;
            *(float4*)(op + 4) = o1;
        }
        // odd dx = 2m+1
#pragma unroll
        for (int m = 0; m < 4; ++m) {
            float4 o0, o1;
            o0.x = acc0[m]       * scale;
            o0.y = accM[0][m].x  * scale;  o0.z = accM[0][m].y * scale;
            o0.w = accM[1][m].x  * scale;
            o1.x = accM[1][m].y  * scale;  o1.y = accM[2][m].x * scale;
            o1.z = accM[2][m].y  * scale;  o1.w = acc7[m]      * scale;
            float* op = ob + (size_t)(2 * m + 1) * HW;
            *(float4*)(op)     = o0;
            *(float4*)(op + 4) = o1;
        }
    }
}

extern "C" void kernel_launch(void* const* d_in, const int* in_sizes, int n_in,
                              void* d_out, int out_size)
{
    const float* fs = (const float*)d_in[0];   // feat_s
    const float* ft = (const float*)d_in[1];   // feat_t
    float* out = (float*)d_out;

    cudaFuncSetAttribute(corr_kernel, cudaFuncAttributeMaxDynamicSharedMemorySize,
                         SMEM_B);

    dim3 grid(NH / TYR, NB);   // (48, 16)
    corr_kernel<<<grid, BLOCK, SMEM_B>>>(fs, ft, out);
}